// round 1
// baseline (speedup 1.0000x reference)
#include <cuda_runtime.h>
#include <cuda_bf16.h>
#include <math.h>

// Problem constants
#define NB   4
#define SEQ  2048
#define DH   1024
#define NH   16
#define HD   64
#define MROWS (NB*SEQ)          // 8192

// ---------------- scratch (static device globals; no allocation) -------------
__device__ float g_xn[MROWS * DH];
__device__ float g_q [MROWS * DH];
__device__ float g_k [MROWS * DH];
__device__ float g_v [MROWS * DH];
__device__ float g_z [MROWS * DH];

// ---------------------------- LayerNorm --------------------------------------
__global__ __launch_bounds__(256) void ln_kernel(
    const float* __restrict__ x, const float* __restrict__ gamma,
    const float* __restrict__ beta, float* __restrict__ xn)
{
    __shared__ float red[256];
    int row = blockIdx.x;
    const float* xr = x + (size_t)row * DH;
    float* outr = xn + (size_t)row * DH;
    int t = threadIdx.x;

    // sum
    float s = 0.f, sq = 0.f;
    #pragma unroll
    for (int i = 0; i < 4; i++) {
        float v = xr[t + i * 256];
        s += v; sq += v * v;
    }
    red[t] = s; __syncthreads();
    for (int off = 128; off > 0; off >>= 1) {
        if (t < off) red[t] += red[t + off];
        __syncthreads();
    }
    float mu = red[0] * (1.0f / DH);
    __syncthreads();
    red[t] = sq; __syncthreads();
    for (int off = 128; off > 0; off >>= 1) {
        if (t < off) red[t] += red[t + off];
        __syncthreads();
    }
    float var = red[0] * (1.0f / DH) - mu * mu;
    float inv = rsqrtf(var + 1e-5f);
    #pragma unroll
    for (int i = 0; i < 4; i++) {
        int c = t + i * 256;
        outr[c] = (xr[c] - mu) * inv * gamma[c] + beta[c];
    }
}

// ------------------------ GEMM: C = A @ W^T + bias ----------------------------
// A: [M, K] row-major, W: [N, K] row-major (so both read along K contiguously)
#define GBM 128
#define GBN 64
#define GBK 16

__global__ __launch_bounds__(256) void gemm_bias_kernel(
    const float* __restrict__ A, const float* __restrict__ W,
    const float* __restrict__ bias, float* __restrict__ C,
    int M, int N, int K)
{
    __shared__ float As[GBK][GBM + 4];
    __shared__ float Bs[GBK][GBN + 4];

    int tid = threadIdx.x;
    int m0 = blockIdx.y * GBM;
    int n0 = blockIdx.x * GBN;
    int tx = tid & 15;        // n direction: 16 threads * 4 cols
    int ty = tid >> 4;        // m direction: 16 threads * 8 rows

    float acc[8][4];
    #pragma unroll
    for (int i = 0; i < 8; i++)
        #pragma unroll
        for (int j = 0; j < 4; j++) acc[i][j] = 0.f;

    for (int k0 = 0; k0 < K; k0 += GBK) {
        // load A tile: 128 rows x 16 cols = 512 float4, 2 per thread
        #pragma unroll
        for (int e = tid; e < (GBM * GBK) / 4; e += 256) {
            int r = e >> 2;
            int c4 = (e & 3) * 4;
            float4 va = *(const float4*)&A[(size_t)(m0 + r) * K + k0 + c4];
            As[c4 + 0][r] = va.x; As[c4 + 1][r] = va.y;
            As[c4 + 2][r] = va.z; As[c4 + 3][r] = va.w;
        }
        // load W tile: 64 rows x 16 cols = 256 float4, 1 per thread
        {
            int r = tid >> 2;
            int c4 = (tid & 3) * 4;
            float4 vb = *(const float4*)&W[(size_t)(n0 + r) * K + k0 + c4];
            Bs[c4 + 0][r] = vb.x; Bs[c4 + 1][r] = vb.y;
            Bs[c4 + 2][r] = vb.z; Bs[c4 + 3][r] = vb.w;
        }
        __syncthreads();

        #pragma unroll
        for (int k = 0; k < GBK; k++) {
            float a[8], b[4];
            #pragma unroll
            for (int i = 0; i < 8; i++) a[i] = As[k][ty * 8 + i];
            #pragma unroll
            for (int j = 0; j < 4; j++) b[j] = Bs[k][tx * 4 + j];
            #pragma unroll
            for (int i = 0; i < 8; i++)
                #pragma unroll
                for (int j = 0; j < 4; j++)
                    acc[i][j] += a[i] * b[j];
        }
        __syncthreads();
    }

    #pragma unroll
    for (int i = 0; i < 8; i++) {
        int m = m0 + ty * 8 + i;
        #pragma unroll
        for (int j = 0; j < 4; j++) {
            int n = n0 + tx * 4 + j;
            C[(size_t)m * N + n] = acc[i][j] + bias[n];
        }
    }
}

// ----------------------------- Attention -------------------------------------
// One block handles (n, h, 4 consecutive query rows). Causal.
#define QC 4
#define KT 32

__global__ __launch_bounds__(256) void attn_kernel(
    const float* __restrict__ q, const float* __restrict__ k,
    const float* __restrict__ v, float* __restrict__ z)
{
    __shared__ float qs[QC][HD];
    __shared__ float ks[KT][HD + 1];
    __shared__ float sc[QC][SEQ];      // scores / probabilities
    __shared__ float red[256];
    __shared__ float rowstat[QC];

    int xc = blockIdx.x;
    int h  = blockIdx.y;
    int n  = blockIdx.z;
    int x0 = xc * QC;
    int t  = threadIdx.x;

    const float* qbase = q + ((size_t)n * SEQ) * DH + h * HD;
    const float* kbase = k + ((size_t)n * SEQ) * DH + h * HD;
    const float* vbase = v + ((size_t)n * SEQ) * DH + h * HD;

    // load 4 query rows (4*64 = 256 floats)
    {
        int qq = t >> 6, d = t & 63;
        qs[qq][d] = qbase[(size_t)(x0 + qq) * DH + d];
    }
    __syncthreads();

    int nY = x0 + QC;   // number of key positions any row in this chunk can see

    for (int y0 = 0; y0 < nY; y0 += KT) {
        // stage KT key rows
        #pragma unroll
        for (int e = t; e < KT * HD; e += 256) {
            int r = e >> 6, d = e & 63;
            int y = y0 + r;
            ks[r][d] = (y < nY) ? kbase[(size_t)y * DH + d] : 0.f;
        }
        __syncthreads();

        if (t < QC * KT) {
            int qq = t >> 5, yy = t & 31;
            int y = y0 + yy;
            if (y < nY) {
                float acc = 0.f;
                #pragma unroll
                for (int d = 0; d < HD; d++) acc += qs[qq][d] * ks[yy][d];
                int x = x0 + qq;
                sc[qq][y] = (y <= x) ? acc * 0.125f : -INFINITY;
            }
        }
        __syncthreads();
    }

    // softmax per row: 64 threads per row
    int qq = t >> 6;
    int lt = t & 63;
    int x = x0 + qq;
    int len = x + 1;

    float m = -INFINITY;
    for (int y = lt; y < len; y += 64) m = fmaxf(m, sc[qq][y]);
    red[t] = m; __syncthreads();
    if (lt == 0) {
        float mm = -INFINITY;
        #pragma unroll
        for (int i = 0; i < 64; i++) mm = fmaxf(mm, red[qq * 64 + i]);
        rowstat[qq] = mm;
    }
    __syncthreads();
    float rm = rowstat[qq];
    float s = 0.f;
    for (int y = lt; y < len; y += 64) {
        float e = __expf(sc[qq][y] - rm);
        sc[qq][y] = e;
        s += e;
    }
    __syncthreads();   // rowstat reuse guard
    red[t] = s; __syncthreads();
    if (lt == 0) {
        float ss = 0.f;
        #pragma unroll
        for (int i = 0; i < 64; i++) ss += red[qq * 64 + i];
        rowstat[qq] = ss;
    }
    __syncthreads();
    float inv = 1.0f / rowstat[qq];

    // PV: thread (qq, d=lt). All lanes of a warp share qq -> coalesced V reads.
    float acc = 0.f;
    int y = 0;
    for (; y + 4 <= len; y += 4) {
        acc += sc[qq][y + 0] * vbase[(size_t)(y + 0) * DH + lt];
        acc += sc[qq][y + 1] * vbase[(size_t)(y + 1) * DH + lt];
        acc += sc[qq][y + 2] * vbase[(size_t)(y + 2) * DH + lt];
        acc += sc[qq][y + 3] * vbase[(size_t)(y + 3) * DH + lt];
    }
    for (; y < len; y++) acc += sc[qq][y] * vbase[(size_t)y * DH + lt];

    z[((size_t)n * SEQ + x) * DH + h * HD + lt] = acc * inv;
}

// ------------------------------ launcher --------------------------------------
extern "C" void kernel_launch(void* const* d_in, const int* in_sizes, int n_in,
                              void* d_out, int out_size)
{
    const float* x     = (const float*)d_in[0];
    const float* Wq    = (const float*)d_in[1];
    const float* bq    = (const float*)d_in[2];
    const float* Wk    = (const float*)d_in[3];
    const float* bk    = (const float*)d_in[4];
    const float* Wv    = (const float*)d_in[5];
    const float* bv    = (const float*)d_in[6];
    const float* Wo    = (const float*)d_in[7];
    const float* bo    = (const float*)d_in[8];
    const float* gamma = (const float*)d_in[9];
    const float* beta  = (const float*)d_in[10];
    float* out = (float*)d_out;

    float *xn, *qp, *kp, *vp, *zp;
    cudaGetSymbolAddress((void**)&xn, g_xn);
    cudaGetSymbolAddress((void**)&qp, g_q);
    cudaGetSymbolAddress((void**)&kp, g_k);
    cudaGetSymbolAddress((void**)&vp, g_v);
    cudaGetSymbolAddress((void**)&zp, g_z);

    // 1. LayerNorm
    ln_kernel<<<MROWS, 256>>>(x, gamma, beta, xn);

    // 2. Q/K/V projections
    dim3 ggrid(DH / GBN, MROWS / GBM);
    gemm_bias_kernel<<<ggrid, 256>>>(xn, Wq, bq, qp, MROWS, DH, DH);
    gemm_bias_kernel<<<ggrid, 256>>>(xn, Wk, bk, kp, MROWS, DH, DH);
    gemm_bias_kernel<<<ggrid, 256>>>(xn, Wv, bv, vp, MROWS, DH, DH);

    // 3. causal multi-head attention
    dim3 agrid(SEQ / QC, NH, NB);
    attn_kernel<<<agrid, 256>>>(qp, kp, vp, zp);

    // 4. output projection
    gemm_bias_kernel<<<ggrid, 256>>>(zp, Wo, bo, out, MROWS, DH, DH);
}

// round 2
// speedup vs baseline: 1.9519x; 1.9519x over previous
#include <cuda_runtime.h>
#include <cuda_bf16.h>
#include <math.h>

// Problem constants
#define NB   4
#define SEQ  2048
#define DH   1024
#define NH   16
#define HD   64
#define MROWS (NB*SEQ)          // 8192

// ---------------- scratch (static device globals; no allocation) -------------
__device__ float g_xn[MROWS * DH];
__device__ float g_q [MROWS * DH];
__device__ float g_k [MROWS * DH];
__device__ float g_v [MROWS * DH];
__device__ float g_z [MROWS * DH];

// ---------------------------- LayerNorm --------------------------------------
__global__ __launch_bounds__(256) void ln_kernel(
    const float* __restrict__ x, const float* __restrict__ gamma,
    const float* __restrict__ beta, float* __restrict__ xn)
{
    __shared__ float red[256];
    int row = blockIdx.x;
    const float* xr = x + (size_t)row * DH;
    float* outr = xn + (size_t)row * DH;
    int t = threadIdx.x;

    float s = 0.f, sq = 0.f;
    #pragma unroll
    for (int i = 0; i < 4; i++) {
        float v = xr[t + i * 256];
        s += v; sq += v * v;
    }
    red[t] = s; __syncthreads();
    for (int off = 128; off > 0; off >>= 1) {
        if (t < off) red[t] += red[t + off];
        __syncthreads();
    }
    float mu = red[0] * (1.0f / DH);
    __syncthreads();
    red[t] = sq; __syncthreads();
    for (int off = 128; off > 0; off >>= 1) {
        if (t < off) red[t] += red[t + off];
        __syncthreads();
    }
    float var = red[0] * (1.0f / DH) - mu * mu;
    float inv = rsqrtf(var + 1e-5f);
    #pragma unroll
    for (int i = 0; i < 4; i++) {
        int c = t + i * 256;
        outr[c] = (xr[c] - mu) * inv * gamma[c] + beta[c];
    }
}

// ------------------------ GEMM: C = A @ W^T + bias ----------------------------
// A: [M, K] row-major, W: [N, K] row-major. 128x128x16 tile, 8x8 microtile.
#define BM 128
#define BN 128
#define BKG 16

__global__ __launch_bounds__(256, 2) void gemm_bias_kernel(
    const float* __restrict__ A, const float* __restrict__ W,
    const float* __restrict__ bias, float* __restrict__ C,
    int M, int N, int K)
{
    __shared__ float As[BKG][132];
    __shared__ float Bs[BKG][132];

    int t  = threadIdx.x;
    int tx = t & 15;
    int ty = t >> 4;
    int m0 = blockIdx.y * BM;
    int n0 = blockIdx.x * BN;

    float acc[8][8];
    #pragma unroll
    for (int i = 0; i < 8; i++)
        #pragma unroll
        for (int j = 0; j < 8; j++) acc[i][j] = 0.f;

    for (int k0 = 0; k0 < K; k0 += BKG) {
        // load tiles: 128 rows x 16 k = 512 float4 each, 2 per thread
        #pragma unroll
        for (int i = 0; i < 2; i++) {
            int e = t + i * 256;
            int m = e >> 2;
            int kq = (e & 3) * 4;
            float4 va = *(const float4*)&A[(size_t)(m0 + m) * K + k0 + kq];
            As[kq + 0][m] = va.x; As[kq + 1][m] = va.y;
            As[kq + 2][m] = va.z; As[kq + 3][m] = va.w;
            float4 vb = *(const float4*)&W[(size_t)(n0 + m) * K + k0 + kq];
            Bs[kq + 0][m] = vb.x; Bs[kq + 1][m] = vb.y;
            Bs[kq + 2][m] = vb.z; Bs[kq + 3][m] = vb.w;
        }
        __syncthreads();

        #pragma unroll
        for (int k = 0; k < BKG; k++) {
            float4 a0 = *(const float4*)&As[k][ty * 4];
            float4 a1 = *(const float4*)&As[k][64 + ty * 4];
            float4 b0 = *(const float4*)&Bs[k][tx * 4];
            float4 b1 = *(const float4*)&Bs[k][64 + tx * 4];
            float a[8] = {a0.x, a0.y, a0.z, a0.w, a1.x, a1.y, a1.z, a1.w};
            float b[8] = {b0.x, b0.y, b0.z, b0.w, b1.x, b1.y, b1.z, b1.w};
            #pragma unroll
            for (int i = 0; i < 8; i++)
                #pragma unroll
                for (int j = 0; j < 8; j++)
                    acc[i][j] += a[i] * b[j];
        }
        __syncthreads();
    }

    float4 bi0 = *(const float4*)&bias[n0 + tx * 4];
    float4 bi1 = *(const float4*)&bias[n0 + 64 + tx * 4];
    float bb[8] = {bi0.x, bi0.y, bi0.z, bi0.w, bi1.x, bi1.y, bi1.z, bi1.w};

    #pragma unroll
    for (int i = 0; i < 8; i++) {
        int m = m0 + ((i < 4) ? (ty * 4 + i) : (64 + ty * 4 + i - 4));
        float4 w0 = make_float4(acc[i][0] + bb[0], acc[i][1] + bb[1],
                                acc[i][2] + bb[2], acc[i][3] + bb[3]);
        float4 w1 = make_float4(acc[i][4] + bb[4], acc[i][5] + bb[5],
                                acc[i][6] + bb[6], acc[i][7] + bb[7]);
        *(float4*)&C[(size_t)m * N + n0 + tx * 4]      = w0;
        *(float4*)&C[(size_t)m * N + n0 + 64 + tx * 4] = w1;
    }
}

// ----------------------------- Flash Attention --------------------------------
// One CTA per (n, h, 128-query tile). Key tiles of 64, online softmax.
#define BQ  128
#define BKT 64
#define QTS 132   // Qt row stride (floats)
#define KTS 68    // Kt row stride
#define PTS 132   // PT row stride
#define ATTN_SMEM ((HD*QTS + HD*KTS + BKT*HD + BKT*PTS) * (int)sizeof(float))

__global__ __launch_bounds__(256, 2) void attn_kernel(
    const float* __restrict__ q, const float* __restrict__ k,
    const float* __restrict__ v, float* __restrict__ z)
{
    extern __shared__ float sm[];
    float* Qt = sm;                     // [64 d][QTS]  (d-major, scaled Q)
    float* Kt = Qt + HD * QTS;          // [64 d][KTS]
    float* Vs = Kt + HD * KTS;          // [64 y][64 d]
    float* PT = Vs + BKT * HD;          // [64 y][PTS]  (P transposed)

    int xc = (gridDim.x - 1) - blockIdx.x;   // heavy tiles first
    int h  = blockIdx.y;
    int n  = blockIdx.z;
    int x0 = xc * BQ;
    int t  = threadIdx.x;
    int tx = t & 15;
    int ty = t >> 4;
    int r0 = ty * 8;    // query rows owned
    int c0 = tx * 4;    // y-cols (S phase) / d-cols (PV phase)

    const float* qb = q + ((size_t)n * SEQ) * DH + h * HD;
    const float* kb = k + ((size_t)n * SEQ) * DH + h * HD;
    const float* vb = v + ((size_t)n * SEQ) * DH + h * HD;

    // load Q tile transposed, scale folded in
    for (int idx = t; idx < BQ * HD; idx += 256) {
        int r = idx >> 6, d = idx & 63;
        Qt[d * QTS + r] = qb[(size_t)(x0 + r) * DH + d] * 0.125f;
    }

    float m_i[8], l_i[8], acc[8][4];
    #pragma unroll
    for (int i = 0; i < 8; i++) {
        m_i[i] = -INFINITY; l_i[i] = 0.f;
        #pragma unroll
        for (int j = 0; j < 4; j++) acc[i][j] = 0.f;
    }

    int yend = x0 + BQ;
    for (int y0 = 0; y0 < yend; y0 += BKT) {
        __syncthreads();   // prior PV done; Qt visible on first iter
        for (int idx = t; idx < BKT * HD; idx += 256) {
            int y = idx >> 6, d = idx & 63;
            Kt[d * KTS + y] = kb[(size_t)(y0 + y) * DH + d];
            Vs[idx]         = vb[(size_t)(y0 + y) * DH + d];
        }
        __syncthreads();

        // ---- S = Q K^T (8x4 microtile) ----
        float s[8][4];
        #pragma unroll
        for (int i = 0; i < 8; i++)
            #pragma unroll
            for (int j = 0; j < 4; j++) s[i][j] = 0.f;

        #pragma unroll 8
        for (int d = 0; d < HD; d++) {
            float4 a0 = *(const float4*)&Qt[d * QTS + r0];
            float4 a1 = *(const float4*)&Qt[d * QTS + r0 + 4];
            float4 bv4 = *(const float4*)&Kt[d * KTS + c0];
            float a[8] = {a0.x, a0.y, a0.z, a0.w, a1.x, a1.y, a1.z, a1.w};
            float b[4] = {bv4.x, bv4.y, bv4.z, bv4.w};
            #pragma unroll
            for (int i = 0; i < 8; i++)
                #pragma unroll
                for (int j = 0; j < 4; j++)
                    s[i][j] += a[i] * b[j];
        }

        // causal mask (only last two tiles can straddle the diagonal)
        if (y0 + BKT - 1 > x0) {
            #pragma unroll
            for (int i = 0; i < 8; i++)
                #pragma unroll
                for (int j = 0; j < 4; j++)
                    if (y0 + c0 + j > x0 + r0 + i) s[i][j] = -INFINITY;
        }

        // ---- online softmax update (row reductions over 16-lane groups) ----
        #pragma unroll
        for (int i = 0; i < 8; i++) {
            float mt = fmaxf(fmaxf(s[i][0], s[i][1]), fmaxf(s[i][2], s[i][3]));
            #pragma unroll
            for (int o = 8; o > 0; o >>= 1)
                mt = fmaxf(mt, __shfl_xor_sync(0xffffffffu, mt, o));
            float mn = fmaxf(m_i[i], mt);
            float alpha = __expf(m_i[i] - mn);
            m_i[i] = mn;
            float rs = 0.f;
            #pragma unroll
            for (int j = 0; j < 4; j++) {
                s[i][j] = __expf(s[i][j] - mn);
                rs += s[i][j];
            }
            #pragma unroll
            for (int o = 8; o > 0; o >>= 1)
                rs += __shfl_xor_sync(0xffffffffu, rs, o);
            l_i[i] = l_i[i] * alpha + rs;
            #pragma unroll
            for (int j = 0; j < 4; j++) acc[i][j] *= alpha;
        }

        // ---- stage P transposed ----
        #pragma unroll
        for (int j = 0; j < 4; j++) {
            int y = c0 + j;
            *(float4*)&PT[y * PTS + r0] =
                make_float4(s[0][j], s[1][j], s[2][j], s[3][j]);
            *(float4*)&PT[y * PTS + r0 + 4] =
                make_float4(s[4][j], s[5][j], s[6][j], s[7][j]);
        }
        __syncthreads();

        // ---- O += P V (8x4 microtile; c0 now indexes head dim) ----
        #pragma unroll 8
        for (int y = 0; y < BKT; y++) {
            float4 p0 = *(const float4*)&PT[y * PTS + r0];
            float4 p1 = *(const float4*)&PT[y * PTS + r0 + 4];
            float4 v4 = *(const float4*)&Vs[y * HD + c0];
            float p[8] = {p0.x, p0.y, p0.z, p0.w, p1.x, p1.y, p1.z, p1.w};
            float vv[4] = {v4.x, v4.y, v4.z, v4.w};
            #pragma unroll
            for (int i = 0; i < 8; i++)
                #pragma unroll
                for (int j = 0; j < 4; j++)
                    acc[i][j] += p[i] * vv[j];
        }
    }

    // ---- normalize + store ----
    #pragma unroll
    for (int i = 0; i < 8; i++) {
        float inv = 1.0f / l_i[i];
        int x = x0 + r0 + i;
        float4 o = make_float4(acc[i][0] * inv, acc[i][1] * inv,
                               acc[i][2] * inv, acc[i][3] * inv);
        *(float4*)&z[((size_t)n * SEQ + x) * DH + h * HD + c0] = o;
    }
}

// ------------------------------ launcher --------------------------------------
extern "C" void kernel_launch(void* const* d_in, const int* in_sizes, int n_in,
                              void* d_out, int out_size)
{
    const float* x     = (const float*)d_in[0];
    const float* Wq    = (const float*)d_in[1];
    const float* bq    = (const float*)d_in[2];
    const float* Wk    = (const float*)d_in[3];
    const float* bk    = (const float*)d_in[4];
    const float* Wv    = (const float*)d_in[5];
    const float* bv    = (const float*)d_in[6];
    const float* Wo    = (const float*)d_in[7];
    const float* bo    = (const float*)d_in[8];
    const float* gamma = (const float*)d_in[9];
    const float* beta  = (const float*)d_in[10];
    float* out = (float*)d_out;

    float *xn, *qp, *kp, *vp, *zp;
    cudaGetSymbolAddress((void**)&xn, g_xn);
    cudaGetSymbolAddress((void**)&qp, g_q);
    cudaGetSymbolAddress((void**)&kp, g_k);
    cudaGetSymbolAddress((void**)&vp, g_v);
    cudaGetSymbolAddress((void**)&zp, g_z);

    cudaFuncSetAttribute(attn_kernel,
                         cudaFuncAttributeMaxDynamicSharedMemorySize, ATTN_SMEM);

    // 1. LayerNorm
    ln_kernel<<<MROWS, 256>>>(x, gamma, beta, xn);

    // 2. Q/K/V projections
    dim3 ggrid(DH / BN, MROWS / BM);
    gemm_bias_kernel<<<ggrid, 256>>>(xn, Wq, bq, qp, MROWS, DH, DH);
    gemm_bias_kernel<<<ggrid, 256>>>(xn, Wk, bk, kp, MROWS, DH, DH);
    gemm_bias_kernel<<<ggrid, 256>>>(xn, Wv, bv, vp, MROWS, DH, DH);

    // 3. causal multi-head attention (flash)
    dim3 agrid(SEQ / BQ, NH, NB);
    attn_kernel<<<agrid, 256, ATTN_SMEM>>>(qp, kp, vp, zp);

    // 4. output projection
    gemm_bias_kernel<<<ggrid, 256>>>(zp, Wo, bo, out, MROWS, DH, DH);
}

// round 3
// speedup vs baseline: 4.0456x; 2.0726x over previous
#include <cuda_runtime.h>
#include <cuda_bf16.h>
#include <math.h>
#include <stdint.h>

// Problem constants
#define NB   4
#define SEQ  2048
#define DH   1024
#define NH   16
#define HD   64
#define MROWS (NB*SEQ)          // 8192

// ---------------- scratch (static device globals; no allocation) -------------
__device__ float g_xn[MROWS * DH];
__device__ float g_q [MROWS * DH];
__device__ float g_k [MROWS * DH];
__device__ float g_v [MROWS * DH];
__device__ float g_z [MROWS * DH];

// ---------------------------- helpers -----------------------------------------
__device__ __forceinline__ float f_tf32(float x) {
    uint32_t r;
    asm("cvt.rna.tf32.f32 %0, %1;" : "=r"(r) : "f"(x));
    return __uint_as_float(r);
}

__device__ __forceinline__ void mma_tf32(float* c, const float* a, const float* b) {
    asm volatile(
        "mma.sync.aligned.m16n8k8.row.col.f32.tf32.tf32.f32 "
        "{%0,%1,%2,%3}, {%4,%5,%6,%7}, {%8,%9}, {%0,%1,%2,%3};\n"
        : "+f"(c[0]), "+f"(c[1]), "+f"(c[2]), "+f"(c[3])
        : "r"(__float_as_uint(a[0])), "r"(__float_as_uint(a[1])),
          "r"(__float_as_uint(a[2])), "r"(__float_as_uint(a[3])),
          "r"(__float_as_uint(b[0])), "r"(__float_as_uint(b[1])));
}

// ---------------------------- LayerNorm --------------------------------------
__global__ __launch_bounds__(256) void ln_kernel(
    const float* __restrict__ x, const float* __restrict__ gamma,
    const float* __restrict__ beta, float* __restrict__ xn)
{
    __shared__ float red[256];
    int row = blockIdx.x;
    const float* xr = x + (size_t)row * DH;
    float* outr = xn + (size_t)row * DH;
    int t = threadIdx.x;

    float s = 0.f, sq = 0.f;
    #pragma unroll
    for (int i = 0; i < 4; i++) {
        float v = xr[t + i * 256];
        s += v; sq += v * v;
    }
    red[t] = s; __syncthreads();
    for (int off = 128; off > 0; off >>= 1) {
        if (t < off) red[t] += red[t + off];
        __syncthreads();
    }
    float mu = red[0] * (1.0f / DH);
    __syncthreads();
    red[t] = sq; __syncthreads();
    for (int off = 128; off > 0; off >>= 1) {
        if (t < off) red[t] += red[t + off];
        __syncthreads();
    }
    float var = red[0] * (1.0f / DH) - mu * mu;
    float inv = rsqrtf(var + 1e-5f);
    #pragma unroll
    for (int i = 0; i < 4; i++) {
        int c = t + i * 256;
        outr[c] = (xr[c] - mu) * inv * gamma[c] + beta[c];
    }
}

// ------------------- GEMM (tf32 tensor cores): C = A @ W^T + bias -------------
// A: [M,K] row-major, W: [N,K] row-major. Tile 128x128x32, 8 warps of 64x32.
#define BKG 32
#define SA  36

__global__ __launch_bounds__(256, 2) void gemm_tf32_kernel(
    const float* __restrict__ A, const float* __restrict__ W,
    const float* __restrict__ bias, float* __restrict__ C,
    int M, int N, int K)
{
    __shared__ float As[128 * SA];
    __shared__ float Bs[128 * SA];

    int t    = threadIdx.x;
    int lane = t & 31;
    int wid  = t >> 5;
    int lr = lane >> 2;     // 0..7
    int lc = lane & 3;      // 0..3
    int wm = wid & 1;       // 2 warps in m
    int wn = wid >> 1;      // 4 warps in n
    int m_base = wm * 64;
    int n_base = wn * 32;
    int m0 = blockIdx.y * 128;
    int n0 = blockIdx.x * 128;

    float acc[4][4][4];
    #pragma unroll
    for (int i = 0; i < 4; i++)
        #pragma unroll
        for (int j = 0; j < 4; j++)
            #pragma unroll
            for (int e = 0; e < 4; e++) acc[i][j][e] = 0.f;

    for (int k0 = 0; k0 < K; k0 += BKG) {
        // stage tiles (convert to tf32 on the way in)
        #pragma unroll
        for (int i = 0; i < 4; i++) {
            int e   = t + i * 256;
            int row = e >> 3;
            int c4  = (e & 7) * 4;
            float4 va = *(const float4*)&A[(size_t)(m0 + row) * K + k0 + c4];
            As[row * SA + c4 + 0] = f_tf32(va.x);
            As[row * SA + c4 + 1] = f_tf32(va.y);
            As[row * SA + c4 + 2] = f_tf32(va.z);
            As[row * SA + c4 + 3] = f_tf32(va.w);
            float4 vb = *(const float4*)&W[(size_t)(n0 + row) * K + k0 + c4];
            Bs[row * SA + c4 + 0] = f_tf32(vb.x);
            Bs[row * SA + c4 + 1] = f_tf32(vb.y);
            Bs[row * SA + c4 + 2] = f_tf32(vb.z);
            Bs[row * SA + c4 + 3] = f_tf32(vb.w);
        }
        __syncthreads();

        #pragma unroll
        for (int kk = 0; kk < BKG / 8; kk++) {
            int kb = kk * 8;
            float a[4][4], b[4][2];
            #pragma unroll
            for (int mf = 0; mf < 4; mf++) {
                int row = m_base + mf * 16 + lr;
                a[mf][0] = As[row * SA + kb + lc];
                a[mf][1] = As[(row + 8) * SA + kb + lc];
                a[mf][2] = As[row * SA + kb + 4 + lc];
                a[mf][3] = As[(row + 8) * SA + kb + 4 + lc];
            }
            #pragma unroll
            for (int nf = 0; nf < 4; nf++) {
                int col = n_base + nf * 8 + lr;
                b[nf][0] = Bs[col * SA + kb + lc];
                b[nf][1] = Bs[col * SA + kb + 4 + lc];
            }
            #pragma unroll
            for (int mf = 0; mf < 4; mf++)
                #pragma unroll
                for (int nf = 0; nf < 4; nf++)
                    mma_tf32(acc[mf][nf], a[mf], b[nf]);
        }
        __syncthreads();
    }

    // epilogue: bias + store
    #pragma unroll
    for (int nf = 0; nf < 4; nf++) {
        int col = n0 + n_base + nf * 8 + 2 * lc;
        float b0 = bias[col], b1 = bias[col + 1];
        #pragma unroll
        for (int mf = 0; mf < 4; mf++) {
            int row = m0 + m_base + mf * 16 + lr;
            float2 lo = make_float2(acc[mf][nf][0] + b0, acc[mf][nf][1] + b1);
            float2 hi = make_float2(acc[mf][nf][2] + b0, acc[mf][nf][3] + b1);
            *(float2*)&C[(size_t)row * N + col]       = lo;
            *(float2*)&C[(size_t)(row + 8) * N + col] = hi;
        }
    }
}

// ------------------- Flash Attention (tf32 tensor cores) -----------------------
// One CTA per (n, h, 128-query tile). 8 warps, each owning a 16-row stripe.
#define BQ  128
#define BKT 64
#define AST 68     // smem row stride (floats)
#define ATTN_SMEM ((BQ*AST + BKT*AST + BKT*AST + BQ*AST) * (int)sizeof(float))

__global__ __launch_bounds__(256, 1) void attn_kernel(
    const float* __restrict__ q, const float* __restrict__ k,
    const float* __restrict__ v, float* __restrict__ z)
{
    extern __shared__ float sm[];
    float* Qs = sm;                    // [128 r][AST] row-major, tf32, scaled
    float* Ks = Qs + BQ * AST;         // [64 y][AST]
    float* Vs = Ks + BKT * AST;        // [64 y][AST]
    float* Ps = Vs + BKT * AST;        // [128 r][AST]  (per-warp private stripes)

    int xc = (gridDim.x - 1) - blockIdx.x;   // heavy tiles first
    int h  = blockIdx.y;
    int n  = blockIdx.z;
    int x0 = xc * BQ;
    int t    = threadIdx.x;
    int lane = t & 31;
    int wid  = t >> 5;
    int lr = lane >> 2;
    int lc = lane & 3;
    int m_base = wid * 16;             // warp's query-row stripe
    float* Pw = Ps + m_base * AST;     // warp-private P staging

    const float* qb = q + ((size_t)n * SEQ) * DH + h * HD;
    const float* kb = k + ((size_t)n * SEQ) * DH + h * HD;
    const float* vb = v + ((size_t)n * SEQ) * DH + h * HD;

    // stage Q (scaled by 1/8, tf32-rounded)
    for (int idx = t; idx < BQ * HD; idx += 256) {
        int r = idx >> 6, d = idx & 63;
        Qs[r * AST + d] = f_tf32(qb[(size_t)(x0 + r) * DH + d] * 0.125f);
    }

    // per-thread state: rows r_lo = m_base+lr, r_hi = +8
    float m_lo = -INFINITY, m_hi = -INFINITY, l_lo = 0.f, l_hi = 0.f;
    float o[8][4];
    #pragma unroll
    for (int nf = 0; nf < 8; nf++)
        #pragma unroll
        for (int e = 0; e < 4; e++) o[nf][e] = 0.f;

    int yend = x0 + BQ;
    for (int y0 = 0; y0 < yend; y0 += BKT) {
        __syncthreads();   // prior iter's reads of Ks/Vs done; Qs visible (iter 0)
        for (int idx = t; idx < BKT * HD; idx += 256) {
            int y = idx >> 6, d = idx & 63;
            Ks[y * AST + d] = f_tf32(kb[(size_t)(y0 + y) * DH + d]);
            Vs[y * AST + d] = f_tf32(vb[(size_t)(y0 + y) * DH + d]);
        }
        __syncthreads();

        // ---- S = Q K^T : warp computes 16 x 64 ----
        float s[8][4];
        #pragma unroll
        for (int nf = 0; nf < 8; nf++)
            #pragma unroll
            for (int e = 0; e < 4; e++) s[nf][e] = 0.f;

        #pragma unroll
        for (int kk = 0; kk < 8; kk++) {
            int kb8 = kk * 8;
            float a[4];
            int row = m_base + lr;
            a[0] = Qs[row * AST + kb8 + lc];
            a[1] = Qs[(row + 8) * AST + kb8 + lc];
            a[2] = Qs[row * AST + kb8 + 4 + lc];
            a[3] = Qs[(row + 8) * AST + kb8 + 4 + lc];
            #pragma unroll
            for (int nf = 0; nf < 8; nf++) {
                float b[2];
                int y = nf * 8 + lr;
                b[0] = Ks[y * AST + kb8 + lc];
                b[1] = Ks[y * AST + kb8 + 4 + lc];
                mma_tf32(s[nf], a, b);
            }
        }

        // ---- causal mask (only straddling tiles) ----
        if (y0 + BKT - 1 > x0) {
            int r_lo = x0 + m_base + lr;
            #pragma unroll
            for (int nf = 0; nf < 8; nf++) {
                int c = y0 + nf * 8 + 2 * lc;
                if (c     > r_lo) s[nf][0] = -INFINITY;
                if (c + 1 > r_lo) s[nf][1] = -INFINITY;
                if (c     > r_lo + 8) s[nf][2] = -INFINITY;
                if (c + 1 > r_lo + 8) s[nf][3] = -INFINITY;
            }
        }

        // ---- online softmax (row groups of 4 lanes) ----
        float mt_lo = -INFINITY, mt_hi = -INFINITY;
        #pragma unroll
        for (int nf = 0; nf < 8; nf++) {
            mt_lo = fmaxf(mt_lo, fmaxf(s[nf][0], s[nf][1]));
            mt_hi = fmaxf(mt_hi, fmaxf(s[nf][2], s[nf][3]));
        }
        #pragma unroll
        for (int off = 1; off <= 2; off <<= 1) {
            mt_lo = fmaxf(mt_lo, __shfl_xor_sync(0xffffffffu, mt_lo, off));
            mt_hi = fmaxf(mt_hi, __shfl_xor_sync(0xffffffffu, mt_hi, off));
        }
        float mn_lo = fmaxf(m_lo, mt_lo);
        float mn_hi = fmaxf(m_hi, mt_hi);
        float al_lo = __expf(m_lo - mn_lo);
        float al_hi = __expf(m_hi - mn_hi);
        m_lo = mn_lo; m_hi = mn_hi;

        float rs_lo = 0.f, rs_hi = 0.f;
        #pragma unroll
        for (int nf = 0; nf < 8; nf++) {
            s[nf][0] = __expf(s[nf][0] - mn_lo);
            s[nf][1] = __expf(s[nf][1] - mn_lo);
            s[nf][2] = __expf(s[nf][2] - mn_hi);
            s[nf][3] = __expf(s[nf][3] - mn_hi);
            rs_lo += s[nf][0] + s[nf][1];
            rs_hi += s[nf][2] + s[nf][3];
        }
        #pragma unroll
        for (int off = 1; off <= 2; off <<= 1) {
            rs_lo += __shfl_xor_sync(0xffffffffu, rs_lo, off);
            rs_hi += __shfl_xor_sync(0xffffffffu, rs_hi, off);
        }
        l_lo = l_lo * al_lo + rs_lo;
        l_hi = l_hi * al_hi + rs_hi;
        #pragma unroll
        for (int nf = 0; nf < 8; nf++) {
            o[nf][0] *= al_lo; o[nf][1] *= al_lo;
            o[nf][2] *= al_hi; o[nf][3] *= al_hi;
        }

        // ---- stage P (warp-private stripe; tf32-rounded) ----
        #pragma unroll
        for (int nf = 0; nf < 8; nf++) {
            int c = nf * 8 + 2 * lc;
            *(float2*)&Pw[lr * AST + c]       =
                make_float2(f_tf32(s[nf][0]), f_tf32(s[nf][1]));
            *(float2*)&Pw[(lr + 8) * AST + c] =
                make_float2(f_tf32(s[nf][2]), f_tf32(s[nf][3]));
        }
        __syncwarp();

        // ---- O += P V : warp computes 16 x 64 ----
        #pragma unroll
        for (int kk = 0; kk < 8; kk++) {
            int kb8 = kk * 8;
            float a[4];
            a[0] = Pw[lr * AST + kb8 + lc];
            a[1] = Pw[(lr + 8) * AST + kb8 + lc];
            a[2] = Pw[lr * AST + kb8 + 4 + lc];
            a[3] = Pw[(lr + 8) * AST + kb8 + 4 + lc];
            #pragma unroll
            for (int nf = 0; nf < 8; nf++) {
                float b[2];
                int d = nf * 8 + lr;
                b[0] = Vs[(kb8 + lc) * AST + d];
                b[1] = Vs[(kb8 + 4 + lc) * AST + d];
                mma_tf32(o[nf], a, b);
            }
        }
        __syncwarp();   // Pw reads done before next iter's overwrite
    }

    // ---- normalize + store ----
    float inv_lo = 1.0f / l_lo;
    float inv_hi = 1.0f / l_hi;
    int r_lo = x0 + m_base + lr;
    #pragma unroll
    for (int nf = 0; nf < 8; nf++) {
        int d = nf * 8 + 2 * lc;
        float* zlo = &z[((size_t)n * SEQ + r_lo) * DH + h * HD + d];
        float* zhi = &z[((size_t)n * SEQ + r_lo + 8) * DH + h * HD + d];
        *(float2*)zlo = make_float2(o[nf][0] * inv_lo, o[nf][1] * inv_lo);
        *(float2*)zhi = make_float2(o[nf][2] * inv_hi, o[nf][3] * inv_hi);
    }
}

// ------------------------------ launcher --------------------------------------
extern "C" void kernel_launch(void* const* d_in, const int* in_sizes, int n_in,
                              void* d_out, int out_size)
{
    const float* x     = (const float*)d_in[0];
    const float* Wq    = (const float*)d_in[1];
    const float* bq    = (const float*)d_in[2];
    const float* Wk    = (const float*)d_in[3];
    const float* bk    = (const float*)d_in[4];
    const float* Wv    = (const float*)d_in[5];
    const float* bv    = (const float*)d_in[6];
    const float* Wo    = (const float*)d_in[7];
    const float* bo    = (const float*)d_in[8];
    const float* gamma = (const float*)d_in[9];
    const float* beta  = (const float*)d_in[10];
    float* out = (float*)d_out;

    float *xn, *qp, *kp, *vp, *zp;
    cudaGetSymbolAddress((void**)&xn, g_xn);
    cudaGetSymbolAddress((void**)&qp, g_q);
    cudaGetSymbolAddress((void**)&kp, g_k);
    cudaGetSymbolAddress((void**)&vp, g_v);
    cudaGetSymbolAddress((void**)&zp, g_z);

    cudaFuncSetAttribute(attn_kernel,
                         cudaFuncAttributeMaxDynamicSharedMemorySize, ATTN_SMEM);

    // 1. LayerNorm
    ln_kernel<<<MROWS, 256>>>(x, gamma, beta, xn);

    // 2. Q/K/V projections (tf32 tensor cores)
    dim3 ggrid(DH / 128, MROWS / 128);
    gemm_tf32_kernel<<<ggrid, 256>>>(xn, Wq, bq, qp, MROWS, DH, DH);
    gemm_tf32_kernel<<<ggrid, 256>>>(xn, Wk, bk, kp, MROWS, DH, DH);
    gemm_tf32_kernel<<<ggrid, 256>>>(xn, Wv, bv, vp, MROWS, DH, DH);

    // 3. causal multi-head attention (flash, tf32 tensor cores)
    dim3 agrid(SEQ / BQ, NH, NB);
    attn_kernel<<<agrid, 256, ATTN_SMEM>>>(qp, kp, vp, zp);

    // 4. output projection
    gemm_tf32_kernel<<<ggrid, 256>>>(zp, Wo, bo, out, MROWS, DH, DH);
}